// round 1
// baseline (speedup 1.0000x reference)
#include <cuda_runtime.h>
#include <math.h>

#define TPB 512
#define G 4

constexpr int S_ = 500;   // seq len
constexpr int B_ = 512;   // batch

// Precomputed tables (device scratch; __device__ globals are allowed)
__device__ float g_tk[2500];          // transformed keys [M=50, K=50]
__device__ float g_attn[1001 * 50];   // attention per question
__device__ float g_c1[1001 * 100];    // W1[:,200:250] @ qe + b1 per question
__device__ float g_ea[4004 * 400];    // [q*4+r][0:200]=erase, [200:400]=add

// ---------------------------------------------------------------------------
// Prep kernels (cheap, run once per launch; deterministic)
// ---------------------------------------------------------------------------

__global__ void prep_tk_k(const float* __restrict__ km, const float* __restrict__ Wk,
                          const float* __restrict__ bk) {
    int i = blockIdx.x * blockDim.x + threadIdx.x;
    if (i < 2500) {
        int m = i / 50, k = i % 50;
        float a = bk[m];
        for (int l = 0; l < 50; l++) a = fmaf(km[l * 50 + k], Wk[m * 50 + l], a);
        g_tk[i] = a;
    }
}

__global__ void prep_attn_k(const float* __restrict__ qet, const float* __restrict__ Wq,
                            const float* __restrict__ bq) {
    __shared__ float qe[50], qu[50], lg[50], red[2];
    int q = blockIdx.x, tid = threadIdx.x;
    if (tid < 50) qe[tid] = qet[q * 50 + tid];
    __syncthreads();
    if (tid < 50) {
        float a = bq[tid];
        for (int l = 0; l < 50; l++) a = fmaf(Wq[tid * 50 + l], qe[l], a);
        qu[tid] = tanhf(a);
    }
    __syncthreads();
    if (tid < 50) {
        float a = 0.f;
        for (int k = 0; k < 50; k++) a = fmaf(g_tk[tid * 50 + k], qu[k], a);
        lg[tid] = a;
    }
    __syncthreads();
    if (tid == 0) {
        float mx = -1e30f;
        for (int m = 0; m < 50; m++) mx = fmaxf(mx, lg[m]);
        float s = 0.f;
        for (int m = 0; m < 50; m++) s += expf(lg[m] - mx);
        red[0] = mx; red[1] = 1.f / s;
    }
    __syncthreads();
    if (tid < 50) g_attn[q * 50 + tid] = expf(lg[tid] - red[0]) * red[1];
}

__global__ void prep_c1_k(const float* __restrict__ qet, const float* __restrict__ W1,
                          const float* __restrict__ b1) {
    int idx = blockIdx.x * blockDim.x + threadIdx.x;
    if (idx < 1001 * 100) {
        int q = idx / 100, j = idx % 100;
        float a = b1[j];
        const float* w = W1 + j * 250 + 200;
        const float* e = qet + q * 50;
        for (int k = 0; k < 50; k++) a = fmaf(w[k], e[k], a);
        g_c1[idx] = a;
    }
}

__global__ void prep_ea_k(const float* __restrict__ Wv, const float* __restrict__ bv,
                          const float* __restrict__ We, const float* __restrict__ be,
                          const float* __restrict__ Wa, const float* __restrict__ ba) {
    __shared__ float ve[200];
    int q = blockIdx.x >> 2, r = blockIdx.x & 3, tid = threadIdx.x;
    for (int v = tid; v < 200; v += blockDim.x) {
        float acc = bv[v];
        if (q > 0) {
#pragma unroll
            for (int c = 0; c < 4; c++) {
                float w = 1.0f - fabsf((float)c - (float)r) * (1.0f / 3.0f);
                if (w > 0.0f) acc = fmaf(w, Wv[v * 4000 + c * 1000 + q - 1], acc);
            }
        }
        ve[v] = acc;
    }
    __syncthreads();
    for (int task = tid; task < 400; task += blockDim.x) {
        int is_e = (task < 200);
        int row = is_e ? task : task - 200;
        const float* wrow = (is_e ? We : Wa) + row * 200;
        float a = is_e ? be[row] : ba[row];
#pragma unroll 4
        for (int k = 0; k < 200; k++) a = fmaf(wrow[k], ve[k], a);
        g_ea[(size_t)blockIdx.x * 400 + task] =
            is_e ? (1.0f / (1.0f + expf(-a))) : tanhf(a);
    }
}

// ---------------------------------------------------------------------------
// Main persistent kernel: 128 blocks x 512 threads, G=4 batch elems per block.
// Vm state lives in shared memory for the full 500-step scan.
// ---------------------------------------------------------------------------

__global__ void __launch_bounds__(TPB, 1)
akvmn_main(const int* __restrict__ questions, const int* __restrict__ responses,
           const float* __restrict__ ivm,
           const float* __restrict__ W1,
           const float* __restrict__ W2, const float* __restrict__ b2,
           const float* __restrict__ Wo, const float* __restrict__ bo,
           float* __restrict__ outF, float* __restrict__ outM,
           float* __restrict__ outL, float* __restrict__ outP) {
    extern __shared__ float sm[];
    float* Vm   = sm;             // G*10000  (Vm[g][m][v], v contiguous)
    float* h_s  = sm + 40000;     // G*200    read vector
    float* at_s = sm + 40800;     // G*52     attention
    float* er_s = sm + 41008;     // G*200    erase
    float* ad_s = sm + 41808;     // G*200    add
    float* c1_s = sm + 42608;     // G*100    qe-half of W1 product
    float* h1_s = sm + 43008;     // G*100    hidden
    float* fe_s = sm + 43408;     // G*52     feat

    const int tid = threadIdx.x;
    const int b0 = blockIdx.x * G;

    // init Vm (broadcast init_value_memory over the G batch elems)
    for (int i = tid; i < G * 10000; i += TPB) Vm[i] = ivm[i % 10000];
    __syncthreads();

    for (int t = 0; t < S_; t++) {
        // ---- S0: gather per-(q,r) tables into smem -------------------------
        for (int i = tid; i < 1000; i += TPB) {
            if (i < 400) {
                int g = i / 100, j4 = i % 100;
                int q = questions[(b0 + g) * S_ + t];
                int r = responses[(b0 + g) * S_ + t];
                float4 x = ((const float4*)(g_ea + (size_t)(q * 4 + r) * 400))[j4];
                if (j4 < 50) *(float4*)&er_s[g * 200 + j4 * 4] = x;
                else         *(float4*)&ad_s[g * 200 + (j4 - 50) * 4] = x;
            } else if (i < 600) {
                int k = i - 400;
                int g = k / 50, m = k % 50;
                int q = questions[(b0 + g) * S_ + t];
                at_s[g * 52 + m] = g_attn[q * 50 + m];
            } else {
                int k = i - 600;
                int g = k / 100, j = k % 100;
                int q = questions[(b0 + g) * S_ + t];
                c1_s[g * 100 + j] = g_c1[q * 100 + j];
            }
        }
        __syncthreads();

        // ---- S1: fused Vm read + update (read uses old Vm) -----------------
        if (tid < 400) {
            int g = tid / 100;
            int v = (tid % 100) * 2;
            float2 e2 = *(const float2*)&er_s[g * 200 + v];
            float2 a2 = *(const float2*)&ad_s[g * 200 + v];
            float rx = 0.f, ry = 0.f;
            float* vp = &Vm[g * 10000 + v];
            const float* ap = &at_s[g * 52];
#pragma unroll 10
            for (int m = 0; m < 50; m++) {
                float2 x = *(float2*)&vp[m * 200];
                float at = ap[m];
                rx = fmaf(at, x.x, rx);
                ry = fmaf(at, x.y, ry);
                x.x = fmaf(at, fmaf(-e2.x, x.x, a2.x), x.x);
                x.y = fmaf(at, fmaf(-e2.y, x.y, a2.y), x.y);
                *(float2*)&vp[m * 200] = x;
            }
            h_s[g * 200 + v]     = rx;
            h_s[g * 200 + v + 1] = ry;
        }
        __syncthreads();

        // ---- S2: h1 = relu(W1[:, :200] @ read + c1); W1 rows amortized x4 --
        if (tid < 400) {
            int row = tid >> 2, kq = tid & 3;      // 100 rows, 4-way k split
            int k0 = kq * 50;
            float acc[G] = {0.f, 0.f, 0.f, 0.f};
            const float2* wr = (const float2*)(W1 + row * 250 + k0);
            unsigned mask = __activemask();
#pragma unroll 5
            for (int kk = 0; kk < 25; kk++) {
                float2 w = wr[kk];
#pragma unroll
                for (int g = 0; g < G; g++) {
                    float2 hh = *(const float2*)&h_s[g * 200 + k0 + kk * 2];
                    acc[g] = fmaf(w.x, hh.x, fmaf(w.y, hh.y, acc[g]));
                }
            }
#pragma unroll
            for (int g = 0; g < G; g++) {
                acc[g] += __shfl_xor_sync(mask, acc[g], 1);
                acc[g] += __shfl_xor_sync(mask, acc[g], 2);
            }
            // lane kq of each quad owns batch element g=kq
            h1_s[kq * 100 + row] = fmaxf(acc[kq] + c1_s[kq * 100 + row], 0.f);
        }
        __syncthreads();

        // ---- S3: feat = W2 @ h1 + b2; write feats output -------------------
        {
            int g = tid >> 7, f = tid & 127;
            if (f < 50) {
                float acc = b2[f];
                const float4* wr = (const float4*)(W2 + f * 100);
                const float4* hp = (const float4*)&h1_s[g * 100];
#pragma unroll 5
                for (int j = 0; j < 25; j++) {
                    float4 w = wr[j], h = hp[j];
                    acc = fmaf(w.x, h.x, fmaf(w.y, h.y, fmaf(w.z, h.z, fmaf(w.w, h.w, acc))));
                }
                fe_s[g * 52 + f] = acc;
                outF[((size_t)(b0 + g) * S_ + t) * 50 + f] = acc;
            }
        }
        __syncthreads();

        // ---- S4: mastery, logits, probs (one warp per g) -------------------
        if (tid < 128) {
            int g = tid >> 5, lane = tid & 31;
            const float* fp = &fe_s[g * 52];
            float v0 = fp[lane];
            float v1 = (lane + 32 < 50) ? fp[lane + 32] : 0.f;
            float s = v0 + v1;
#pragma unroll
            for (int o = 16; o; o >>= 1) s += __shfl_xor_sync(0xffffffffu, s, o);
            if (lane == 0) outM[(size_t)(b0 + g) * S_ + t] = s * (1.f / 50.f);

            float lgt = -1e30f;
            if (lane < 4) {
                float a = bo[lane];
                const float* w = Wo + lane * 50;
#pragma unroll 10
                for (int f = 0; f < 50; f++) a = fmaf(w[f], fp[f], a);
                lgt = a;
            }
            float mx = lgt;
            mx = fmaxf(mx, __shfl_xor_sync(0xffffffffu, mx, 1));
            mx = fmaxf(mx, __shfl_xor_sync(0xffffffffu, mx, 2));
            float e = (lane < 4) ? expf(lgt - mx) : 0.f;
            float se = e;
            se += __shfl_xor_sync(0xffffffffu, se, 1);
            se += __shfl_xor_sync(0xffffffffu, se, 2);
            if (lane < 4) {
                size_t o = ((size_t)(b0 + g) * S_ + t) * 4 + lane;
                outL[o] = lgt;
                outP[o] = e / se;
            }
        }
        __syncthreads();
    }
}

// ---------------------------------------------------------------------------

extern "C" void kernel_launch(void* const* d_in, const int* in_sizes, int n_in,
                              void* d_out, int out_size) {
    const int*   questions = (const int*)d_in[0];
    const int*   responses = (const int*)d_in[1];
    const float* qet       = (const float*)d_in[2];   // q_embed_table [1001,50]
    const float* Wv        = (const float*)d_in[3];   // [200,4000]
    const float* bv        = (const float*)d_in[4];
    const float* km        = (const float*)d_in[5];   // key_memory [50,50]
    const float* ivm       = (const float*)d_in[6];   // init_value_memory [50,200]
    const float* Wq        = (const float*)d_in[7];
    const float* bq        = (const float*)d_in[8];
    const float* Wk        = (const float*)d_in[9];
    const float* bk        = (const float*)d_in[10];
    const float* We        = (const float*)d_in[11];
    const float* be        = (const float*)d_in[12];
    const float* Wa        = (const float*)d_in[13];
    const float* ba        = (const float*)d_in[14];
    const float* W1        = (const float*)d_in[15];  // [100,250]
    const float* b1        = (const float*)d_in[16];
    const float* W2        = (const float*)d_in[17];  // [50,100]
    const float* b2        = (const float*)d_in[18];
    const float* Wo        = (const float*)d_in[19];  // [4,50]
    const float* bo        = (const float*)d_in[20];

    float* out   = (float*)d_out;
    float* outF  = out;                                  // [512,500,50]
    float* outM  = out + (size_t)512 * 500 * 50;         // [512,500]
    float* outL  = outM + (size_t)512 * 500;             // [512,500,4]
    float* outP  = outL + (size_t)512 * 500 * 4;         // [512,500,4]

    const int smem_bytes = 43616 * 4;                    // 174,464 B dynamic smem
    cudaFuncSetAttribute(akvmn_main, cudaFuncAttributeMaxDynamicSharedMemorySize,
                         smem_bytes);

    // Precompute tables (stream-ordered before main kernel)
    prep_tk_k<<<(2500 + 127) / 128, 128>>>(km, Wk, bk);
    prep_attn_k<<<1001, 64>>>(qet, Wq, bq);
    prep_c1_k<<<(1001 * 100 + 255) / 256, 256>>>(qet, W1, b1);
    prep_ea_k<<<4004, 256>>>(Wv, bv, We, be, Wa, ba);

    akvmn_main<<<512 / G, TPB, smem_bytes>>>(
        questions, responses, ivm, W1, W2, b2, Wo, bo,
        outF, outM, outL, outP);
}

// round 2
// speedup vs baseline: 1.9782x; 1.9782x over previous
#include <cuda_runtime.h>
#include <math.h>

#define TPB 512
#define G 4
constexpr int S_ = 500;
constexpr int VSTR = 10008;   // padded g-stride for Vm (bank-conflict-free float4)

// Device scratch tables
__device__ float g_tk[2500];            // transformed keys [50,50]
__device__ float g_attn[1001 * 52];     // attention per question (padded to 52)
__device__ float g_c1[1001 * 100];      // W1[:,200:250]@qe + b1 per question
__device__ float g_ve[4004 * 200];      // value-embed per (q,r)
__device__ float g_ea[(size_t)4004 * 400]; // [qr][0:200]=erase, [200:400]=add

// ---------------------------------------------------------------------------
// Prep kernels
// ---------------------------------------------------------------------------

__global__ void prep_tk_k(const float* __restrict__ km, const float* __restrict__ Wk,
                          const float* __restrict__ bk) {
    int i = blockIdx.x * blockDim.x + threadIdx.x;
    if (i < 2500) {
        int m = i / 50, k = i % 50;
        float a = bk[m];
        for (int l = 0; l < 50; l++) a = fmaf(km[l * 50 + k], Wk[m * 50 + l], a);
        g_tk[i] = a;
    }
}

__global__ void prep_attn_k(const float* __restrict__ qet, const float* __restrict__ Wq,
                            const float* __restrict__ bq) {
    __shared__ float qe[50], qu[50], lg[50], red[2];
    int q = blockIdx.x, tid = threadIdx.x;
    if (tid < 50) qe[tid] = qet[q * 50 + tid];
    __syncthreads();
    if (tid < 50) {
        float a = bq[tid];
        for (int l = 0; l < 50; l++) a = fmaf(Wq[tid * 50 + l], qe[l], a);
        qu[tid] = tanhf(a);
    }
    __syncthreads();
    if (tid < 50) {
        float a = 0.f;
        for (int k = 0; k < 50; k++) a = fmaf(g_tk[tid * 50 + k], qu[k], a);
        lg[tid] = a;
    }
    __syncthreads();
    if (tid == 0) {
        float mx = -1e30f;
        for (int m = 0; m < 50; m++) mx = fmaxf(mx, lg[m]);
        float s = 0.f;
        for (int m = 0; m < 50; m++) s += expf(lg[m] - mx);
        red[0] = mx; red[1] = 1.f / s;
    }
    __syncthreads();
    if (tid < 52) {
        float v = (tid < 50) ? expf(lg[tid] - red[0]) * red[1] : 0.f;
        g_attn[q * 52 + tid] = v;
    }
}

__global__ void prep_c1_k(const float* __restrict__ qet, const float* __restrict__ W1,
                          const float* __restrict__ b1) {
    int idx = blockIdx.x * blockDim.x + threadIdx.x;
    if (idx < 1001 * 100) {
        int q = idx / 100, j = idx % 100;
        float a = b1[j];
        const float* w = W1 + j * 250 + 200;
        const float* e = qet + q * 50;
        for (int k = 0; k < 50; k++) a = fmaf(w[k], e[k], a);
        g_c1[idx] = a;
    }
}

__global__ void prep_ve_k(const float* __restrict__ Wv, const float* __restrict__ bv) {
    int idx = blockIdx.x * blockDim.x + threadIdx.x;
    if (idx < 4004 * 200) {
        int i = idx / 200, v = idx % 200;
        int q = i >> 2, r = i & 3;
        float acc = bv[v];
        if (q > 0) {
#pragma unroll
            for (int c = 0; c < 4; c++) {
                float w = 1.0f - fabsf((float)(c - r)) * (1.0f / 3.0f);
                if (w > 0.0f) acc = fmaf(w, Wv[v * 4000 + c * 1000 + q - 1], acc);
            }
        }
        g_ve[idx] = acc;
    }
}

// C[i][j] = act( VE[i,:] . W'[j,:] + b'[j] ), W' = [We; Wa], act = sigmoid|tanh
__global__ void prep_ea_gemm(const float* __restrict__ We, const float* __restrict__ be,
                             const float* __restrict__ Wa, const float* __restrict__ ba) {
    __shared__ float As[16][64];
    __shared__ float Bs[16][64];
    int i0 = blockIdx.x * 64, j0 = blockIdx.y * 64;
    int tid = threadIdx.x;
    int ty = tid >> 4, tx = tid & 15;
    float acc[4][4] = {};
    for (int kb = 0; kb < 200; kb += 16) {
        for (int l = tid; l < 1024; l += 256) {
            int r = l >> 4, c = l & 15;
            int gi = i0 + r, gk = kb + c;
            As[c][r] = (gi < 4004 && gk < 200) ? g_ve[gi * 200 + gk] : 0.f;
            int gj = j0 + r;
            float bval = 0.f;
            if (gj < 400 && gk < 200)
                bval = (gj < 200) ? We[gj * 200 + gk] : Wa[(gj - 200) * 200 + gk];
            Bs[c][r] = bval;
        }
        __syncthreads();
#pragma unroll
        for (int k = 0; k < 16; k++) {
            float a[4], b[4];
#pragma unroll
            for (int u = 0; u < 4; u++) a[u] = As[k][ty * 4 + u];
#pragma unroll
            for (int u = 0; u < 4; u++) b[u] = Bs[k][tx * 4 + u];
#pragma unroll
            for (int u = 0; u < 4; u++)
#pragma unroll
                for (int v = 0; v < 4; v++) acc[u][v] = fmaf(a[u], b[v], acc[u][v]);
        }
        __syncthreads();
    }
#pragma unroll
    for (int u = 0; u < 4; u++) {
        int gi = i0 + ty * 4 + u;
        if (gi >= 4004) break;
#pragma unroll
        for (int v = 0; v < 4; v++) {
            int gj = j0 + tx * 4 + v;
            if (gj >= 400) continue;
            float x = acc[u][v] + ((gj < 200) ? be[gj] : ba[gj - 200]);
            g_ea[(size_t)gi * 400 + gj] =
                (gj < 200) ? (1.0f / (1.0f + expf(-x))) : tanhf(x);
        }
    }
}

// ---------------------------------------------------------------------------
// Main persistent kernel
// ---------------------------------------------------------------------------

// smem offsets (in floats)
#define O_VM   0
#define O_W2S  (G * VSTR)                 // 40032
#define O_QS   (O_W2S + 5000)             // 45032 (int)
#define O_RS   (O_QS + 2000)              // 47032 (int)
#define O_EA0  (O_RS + 2000)              // 49032
#define O_EA1  (O_EA0 + 1600)
#define O_AT0  (O_EA1 + 1600)
#define O_AT1  (O_AT0 + 208)
#define O_C10  (O_AT1 + 208)
#define O_C11  (O_C10 + 400)
#define O_HS   (O_C11 + 400)              // 53448
#define O_H1S  (O_HS + 800)
#define O_FES  (O_H1S + 400)
#define SMEM_F (O_FES + 208)              // 54856 floats = 219424 B

__device__ __forceinline__ void cp16(float* dst, const float* src) {
    unsigned d = (unsigned)__cvta_generic_to_shared(dst);
    asm volatile("cp.async.ca.shared.global [%0], [%1], 16;\n" :: "r"(d), "l"(src));
}

__global__ void __launch_bounds__(TPB, 1)
akvmn_main(const int* __restrict__ questions, const int* __restrict__ responses,
           const float* __restrict__ ivm,
           const float* __restrict__ W1, const float* __restrict__ W2,
           const float* __restrict__ b2,
           const float* __restrict__ Wo, const float* __restrict__ bo,
           float* __restrict__ outF, float* __restrict__ outM,
           float* __restrict__ outL, float* __restrict__ outP) {
    extern __shared__ float sm[];
    float* Vm   = sm + O_VM;
    float* W2s  = sm + O_W2S;
    int*   qs   = (int*)(sm + O_QS);
    int*   rs   = (int*)(sm + O_RS);
    float* h_s  = sm + O_HS;
    float* h1_s = sm + O_H1S;
    float* fe_s = sm + O_FES;

    const int tid = threadIdx.x;
    const int b0 = blockIdx.x * G;

    // ---- one-time setup ---------------------------------------------------
    for (int i = tid; i < 10000; i += TPB) {
        float v = ivm[i];
#pragma unroll
        for (int g = 0; g < G; g++) Vm[g * VSTR + i] = v;
    }
    for (int i = tid; i < 5000; i += TPB) W2s[i] = W2[i];
    for (int i = tid; i < G * S_; i += TPB) {
        qs[i] = questions[b0 * S_ + i];
        rs[i] = responses[b0 * S_ + i];
    }

    // W1 k-slice in registers (constant over all steps)
    float2 w1r[25];
    if (tid < 400) {
        int row = tid >> 2, kq = tid & 3;
        const float2* src = (const float2*)(W1 + row * 250 + kq * 50);
#pragma unroll
        for (int j = 0; j < 25; j++) w1r[j] = src[j];
    }
    __syncthreads();

    // ---- prefetch step 0 --------------------------------------------------
    {
        float* ea_d = sm + O_EA0;
        float* at_d = sm + O_AT0;
        float* c1_d = sm + O_C10;
        for (int i = tid; i < 552; i += TPB) {
            if (i < 400) {
                int g = i / 100, j = i % 100;
                int q = qs[g * S_], r = rs[g * S_];
                cp16(ea_d + g * 400 + j * 4, g_ea + (size_t)(q * 4 + r) * 400 + j * 4);
            } else if (i < 500) {
                int k = i - 400, g = k / 25, j = k % 25;
                cp16(c1_d + g * 100 + j * 4, g_c1 + qs[g * S_] * 100 + j * 4);
            } else {
                int k = i - 500, g = k / 13, j = k % 13;
                cp16(at_d + g * 52 + j * 4, g_attn + qs[g * S_] * 52 + j * 4);
            }
        }
    }
    asm volatile("cp.async.commit_group;\n" ::: "memory");

    for (int t = 0; t < S_; t++) {
        asm volatile("cp.async.wait_group 0;\n" ::: "memory");
        __syncthreads();
        const int cur = t & 1;
        const float* ea_c = sm + (cur ? O_EA1 : O_EA0);
        const float* at_c = sm + (cur ? O_AT1 : O_AT0);
        const float* c1_c = sm + (cur ? O_C11 : O_C10);

        // prefetch t+1 into the other buffer (overlaps with compute below)
        if (t + 1 < S_) {
            float* ea_d = sm + (cur ? O_EA0 : O_EA1);
            float* at_d = sm + (cur ? O_AT0 : O_AT1);
            float* c1_d = sm + (cur ? O_C10 : O_C11);
            int t1 = t + 1;
            for (int i = tid; i < 552; i += TPB) {
                if (i < 400) {
                    int g = i / 100, j = i % 100;
                    int q = qs[g * S_ + t1], r = rs[g * S_ + t1];
                    cp16(ea_d + g * 400 + j * 4, g_ea + (size_t)(q * 4 + r) * 400 + j * 4);
                } else if (i < 500) {
                    int k = i - 400, g = k / 25, j = k % 25;
                    cp16(c1_d + g * 100 + j * 4, g_c1 + qs[g * S_ + t1] * 100 + j * 4);
                } else {
                    int k = i - 500, g = k / 13, j = k % 13;
                    cp16(at_d + g * 52 + j * 4, g_attn + qs[g * S_ + t1] * 52 + j * 4);
                }
            }
        }
        asm volatile("cp.async.commit_group;\n" ::: "memory");

        // ---- S1: fused Vm read + update (float4 lanes) ---------------------
        if (tid < 200) {
            int g = tid / 50, vq = tid % 50, v0 = vq * 4;
            const float* eac = ea_c + g * 400;
            float4 e4 = *(const float4*)(eac + v0);
            float4 a4 = *(const float4*)(eac + 200 + v0);
            const float* atp = at_c + g * 52;
            float* vp = Vm + g * VSTR + v0;
            float4 r4 = make_float4(0.f, 0.f, 0.f, 0.f);
#pragma unroll 5
            for (int m = 0; m < 50; m++) {
                float4 x = *(float4*)(vp + m * 200);
                float at = atp[m];
                r4.x = fmaf(at, x.x, r4.x);
                r4.y = fmaf(at, x.y, r4.y);
                r4.z = fmaf(at, x.z, r4.z);
                r4.w = fmaf(at, x.w, r4.w);
                x.x = fmaf(at, fmaf(-e4.x, x.x, a4.x), x.x);
                x.y = fmaf(at, fmaf(-e4.y, x.y, a4.y), x.y);
                x.z = fmaf(at, fmaf(-e4.z, x.z, a4.z), x.z);
                x.w = fmaf(at, fmaf(-e4.w, x.w, a4.w), x.w);
                *(float4*)(vp + m * 200) = x;
            }
            *(float4*)(h_s + g * 200 + v0) = r4;
        }
        __syncthreads();

        // ---- S2: h1 = relu(W1[:, :200]@read + c1), W1 in registers ---------
        if (tid < 400) {
            int row = tid >> 2, kq = tid & 3, k0 = kq * 50;
            float a0 = 0.f, a1 = 0.f, a2 = 0.f, a3 = 0.f;
#pragma unroll
            for (int kk = 0; kk < 25; kk++) {
                float2 w = w1r[kk];
                float2 h0 = *(const float2*)(h_s + 0 * 200 + k0 + kk * 2);
                float2 h1 = *(const float2*)(h_s + 1 * 200 + k0 + kk * 2);
                float2 h2 = *(const float2*)(h_s + 2 * 200 + k0 + kk * 2);
                float2 h3 = *(const float2*)(h_s + 3 * 200 + k0 + kk * 2);
                a0 = fmaf(w.x, h0.x, fmaf(w.y, h0.y, a0));
                a1 = fmaf(w.x, h1.x, fmaf(w.y, h1.y, a1));
                a2 = fmaf(w.x, h2.x, fmaf(w.y, h2.y, a2));
                a3 = fmaf(w.x, h3.x, fmaf(w.y, h3.y, a3));
            }
            unsigned msk = __activemask();
            float acc[G] = {a0, a1, a2, a3};
#pragma unroll
            for (int g = 0; g < G; g++) {
                acc[g] += __shfl_xor_sync(msk, acc[g], 1);
                acc[g] += __shfl_xor_sync(msk, acc[g], 2);
            }
            h1_s[kq * 100 + row] = fmaxf(acc[kq] + c1_c[kq * 100 + row], 0.f);
        }
        __syncthreads();

        // ---- S3: feat = W2@h1 + b2 (W2 broadcast across g-lanes) -----------
        if (tid < 200) {
            int f = tid >> 2, g = tid & 3;
            float acc = b2[f];
#pragma unroll
            for (int j = 0; j < 25; j++) {
                float4 w = *(const float4*)(W2s + f * 100 + j * 4);
                float4 h = *(const float4*)(h1_s + g * 100 + j * 4);
                acc = fmaf(w.x, h.x, fmaf(w.y, h.y, fmaf(w.z, h.z, fmaf(w.w, h.w, acc))));
            }
            fe_s[g * 52 + f] = acc;
            outF[((size_t)(b0 + g) * S_ + t) * 50 + f] = acc;
        }
        __syncthreads();

        // ---- S4: mastery / logits / probs (one warp per g) -----------------
        if (tid < 128) {
            int g = tid >> 5, lane = tid & 31;
            const float* fp = fe_s + g * 52;
            float v0 = fp[lane];
            float v1 = (lane + 32 < 50) ? fp[lane + 32] : 0.f;
            float s = v0 + v1;
#pragma unroll
            for (int o = 16; o; o >>= 1) s += __shfl_xor_sync(0xffffffffu, s, o);
            if (lane == 0) outM[(size_t)(b0 + g) * S_ + t] = s * (1.f / 50.f);

            float lgt = -1e30f;
            if (lane < 4) {
                float a = bo[lane];
                const float* w = Wo + lane * 50;
#pragma unroll 10
                for (int f = 0; f < 50; f++) a = fmaf(w[f], fp[f], a);
                lgt = a;
            }
            float mx = lgt;
            mx = fmaxf(mx, __shfl_xor_sync(0xffffffffu, mx, 1));
            mx = fmaxf(mx, __shfl_xor_sync(0xffffffffu, mx, 2));
            float e = (lane < 4) ? expf(lgt - mx) : 0.f;
            float se = e;
            se += __shfl_xor_sync(0xffffffffu, se, 1);
            se += __shfl_xor_sync(0xffffffffu, se, 2);
            if (lane < 4) {
                size_t o = ((size_t)(b0 + g) * S_ + t) * 4 + lane;
                outL[o] = lgt;
                outP[o] = e / se;
            }
        }
        __syncthreads();
    }
}

// ---------------------------------------------------------------------------

extern "C" void kernel_launch(void* const* d_in, const int* in_sizes, int n_in,
                              void* d_out, int out_size) {
    const int*   questions = (const int*)d_in[0];
    const int*   responses = (const int*)d_in[1];
    const float* qet       = (const float*)d_in[2];
    const float* Wv        = (const float*)d_in[3];
    const float* bv        = (const float*)d_in[4];
    const float* km        = (const float*)d_in[5];
    const float* ivm       = (const float*)d_in[6];
    const float* Wq        = (const float*)d_in[7];
    const float* bq        = (const float*)d_in[8];
    const float* Wk        = (const float*)d_in[9];
    const float* bk        = (const float*)d_in[10];
    const float* We        = (const float*)d_in[11];
    const float* be        = (const float*)d_in[12];
    const float* Wa        = (const float*)d_in[13];
    const float* ba        = (const float*)d_in[14];
    const float* W1        = (const float*)d_in[15];
    const float* b1        = (const float*)d_in[16];
    const float* W2        = (const float*)d_in[17];
    const float* b2        = (const float*)d_in[18];
    const float* Wo        = (const float*)d_in[19];
    const float* bo        = (const float*)d_in[20];

    float* out  = (float*)d_out;
    float* outF = out;
    float* outM = out + (size_t)512 * 500 * 50;
    float* outL = outM + (size_t)512 * 500;
    float* outP = outL + (size_t)512 * 500 * 4;

    const int smem_bytes = SMEM_F * 4;
    cudaFuncSetAttribute(akvmn_main, cudaFuncAttributeMaxDynamicSharedMemorySize,
                         smem_bytes);

    prep_tk_k<<<(2500 + 127) / 128, 128>>>(km, Wk, bk);
    prep_attn_k<<<1001, 64>>>(qet, Wq, bq);
    prep_c1_k<<<(1001 * 100 + 255) / 256, 256>>>(qet, W1, b1);
    prep_ve_k<<<(4004 * 200 + 255) / 256, 256>>>(Wv, bv);
    {
        dim3 grid((4004 + 63) / 64, (400 + 63) / 64);
        prep_ea_gemm<<<grid, 256>>>(We, be, Wa, ba);
    }

    akvmn_main<<<512 / G, TPB, smem_bytes>>>(
        questions, responses, ivm, W1, W2, b2, Wo, bo,
        outF, outM, outL, outP);
}